// round 13
// baseline (speedup 1.0000x reference)
#include <cuda_runtime.h>
#include <cuda_fp16.h>
#include <math.h>
#include <stdint.h>

#define N_NODES 100000
#define N_EDGES 3200000
#define D_IN    512
#define D_HID   256
#define D_OUT   64
#define KORD    10

#define SCAN_CHUNK   1024
#define NSCAN_BLOCKS ((N_NODES + SCAN_CHUNK - 1) / SCAN_CHUNK)   // 98

// ---------------- device scratch (no allocations allowed) ----------------
__device__ int     g_cnt[N_NODES];
__device__ int     g_pos[N_NODES];
__device__ int     g_start[N_NODES + 1];
__device__ float   g_dinv[N_NODES];
__device__ int     g_bsum[NSCAN_BLOCKS];
__device__ int     g_boff[NSCAN_BLOCKS];
__device__ int2    g_edge[N_EDGES];                        // (col, w bits) CSR by row
__device__ __half  g_w1h[(size_t)D_HID * D_IN];            // W1^T fp16 [256][512]
__device__ __half  g_w2h[(size_t)D_OUT * D_HID];           // W2^T fp16 [64][256]
__device__ __half  g_h1h[(size_t)N_NODES * D_HID];         // MLP hidden fp16
__device__ float   g_h [(size_t)N_NODES * D_OUT];          // MLP output fp32
__device__ __half2 g_hh[(size_t)N_NODES * (D_OUT / 2)];    // MLP output fp16
__device__ __half2 g_q0[(size_t)N_NODES * (D_OUT / 2)];    // Horner intermediates (fp16)
__device__ __half2 g_q1[(size_t)N_NODES * (D_OUT / 2)];
__device__ float   g_coef[KORD + 1];                       // monomial coeffs of poly in A

// ---------------- CSR build ----------------
__global__ void zero_cnt_k() {
    int i = blockIdx.x * blockDim.x + threadIdx.x;
    if (i < N_NODES) g_cnt[i] = 0;
}

// 2 edges per thread
__global__ void hist_k(const int* __restrict__ row) {
    int t = blockIdx.x * blockDim.x + threadIdx.x;
    int e0 = t * 2;
    if (e0 >= N_EDGES) return;
    int2 r2 = *reinterpret_cast<const int2*>(&row[e0]);
    atomicAdd(&g_cnt[r2.x], 1);
    atomicAdd(&g_cnt[r2.y], 1);
}

// --- multi-block exclusive scan over g_cnt ---
__global__ void scanA_k() {
    __shared__ int ws[8];
    int b    = blockIdx.x;
    int tid  = threadIdx.x;
    int lane = tid & 31, warp = tid >> 5;
    int base = b * SCAN_CHUNK + tid * 4;
    int s = 0;
#pragma unroll
    for (int q = 0; q < 4; q++) {
        int i = base + q;
        if (i < N_NODES) s += g_cnt[i];
    }
#pragma unroll
    for (int o = 16; o; o >>= 1) s += __shfl_xor_sync(0xFFFFFFFFu, s, o);
    if (lane == 0) ws[warp] = s;
    __syncthreads();
    if (tid == 0) {
        int t = 0;
#pragma unroll
        for (int q = 0; q < 8; q++) t += ws[q];
        g_bsum[b] = t;
    }
}

__global__ void scanB_k() {
    __shared__ int ws[4];
    int tid = threadIdx.x, lane = tid & 31, warp = tid >> 5;   // 128 threads
    int v = (tid < NSCAN_BLOCKS) ? g_bsum[tid] : 0;
    int incl = v;
#pragma unroll
    for (int o = 1; o < 32; o <<= 1) {
        int t = __shfl_up_sync(0xFFFFFFFFu, incl, o);
        if (lane >= o) incl += t;
    }
    if (lane == 31) ws[warp] = incl;
    __syncthreads();
    if (warp == 0 && lane < 4) {
        int w = ws[lane];
#pragma unroll
        for (int o = 1; o < 4; o <<= 1) {
            int t = __shfl_up_sync(0xFu, w, o);
            if (lane >= o) w += t;
        }
        ws[lane] = w;
    }
    __syncthreads();
    int woff = (warp > 0) ? ws[warp - 1] : 0;
    if (tid < NSCAN_BLOCKS) g_boff[tid] = woff + incl - v;
    if (tid == 0) g_start[N_NODES] = N_EDGES;
}

__global__ void scanC_k() {
    __shared__ int ws[8];
    int b    = blockIdx.x;
    int tid  = threadIdx.x;
    int lane = tid & 31, warp = tid >> 5;
    int base = b * SCAN_CHUNK + tid * 4;
    int v[4];
    int ts = 0;
#pragma unroll
    for (int q = 0; q < 4; q++) {
        int i = base + q;
        v[q] = (i < N_NODES) ? g_cnt[i] : 0;
        ts += v[q];
    }
    int incl = ts;
#pragma unroll
    for (int o = 1; o < 32; o <<= 1) {
        int t = __shfl_up_sync(0xFFFFFFFFu, incl, o);
        if (lane >= o) incl += t;
    }
    if (lane == 31) ws[warp] = incl;
    __syncthreads();
    if (warp == 0 && lane < 8) {
        int w = ws[lane];
#pragma unroll
        for (int o = 1; o < 8; o <<= 1) {
            int t = __shfl_up_sync(0xFFu, w, o);
            if (lane >= o) w += t;
        }
        ws[lane] = w;
    }
    __syncthreads();
    int off = g_boff[b] + ((warp > 0) ? ws[warp - 1] : 0) + (incl - ts);
#pragma unroll
    for (int q = 0; q < 4; q++) {
        int i = base + q;
        if (i < N_NODES) {
            g_start[i] = off;
            g_pos[i]   = off;
            g_dinv[i]  = (v[q] > 0) ? rsqrtf((float)v[q]) : 0.0f;
        }
        off += v[q];
    }
}

// 2 edges per thread
__global__ void scatter_k(const int* __restrict__ row, const int* __restrict__ col) {
    int t = blockIdx.x * blockDim.x + threadIdx.x;
    int e0 = t * 2;
    if (e0 >= N_EDGES) return;
    int2 r2 = *reinterpret_cast<const int2*>(&row[e0]);
    int2 c2 = *reinterpret_cast<const int2*>(&col[e0]);
    int p0 = atomicAdd(&g_pos[r2.x], 1);
    g_edge[p0] = make_int2(c2.x, __float_as_int(g_dinv[r2.x] * g_dinv[c2.x]));
    int p1 = atomicAdd(&g_pos[r2.y], 1);
    g_edge[p1] = make_int2(c2.y, __float_as_int(g_dinv[r2.y] * g_dinv[c2.y]));
}

// ---------------- W1/W2 -> fp16 transposed ----------------
__global__ void convW_k(const float* __restrict__ W1, const float* __restrict__ W2) {
    int i = blockIdx.x * blockDim.x + threadIdx.x;
    if (i < D_IN * D_HID) {
        int k = i / D_HID, n = i % D_HID;          // W1[k][n]
        g_w1h[(size_t)n * D_IN + k] = __float2half_rn(W1[i]);
    }
    int j = i - D_IN * D_HID;
    if (j >= 0 && j < D_HID * D_OUT) {
        int k = j / D_OUT, n = j % D_OUT;          // W2[k][n]
        g_w2h[(size_t)n * D_HID + k] = __float2half_rn(W2[j]);
    }
}

// ---------------- Bernstein -> monomial coefficients (exact in double) ----------------
__global__ void coef_k(const float* __restrict__ temp) {
    if (threadIdx.x != 0 || blockIdx.x != 0) return;
    double B[KORD + 1][KORD + 1];
    for (int n = 0; n <= KORD; n++) {
        for (int j = 0; j <= KORD; j++) B[n][j] = 0.0;
        B[n][0] = 1.0;
        for (int j = 1; j <= n; j++)
            B[n][j] = (j == n) ? 1.0 : (B[n - 1][j - 1] + B[n - 1][j]);
    }
    double a[KORD + 1];
    for (int j = 0; j <= KORD; j++) a[j] = 0.0;
    for (int k = 0; k <= KORD; k++) {
        double th = (double)temp[k];
        if (th < 0.0) th = 0.0;                       // relu
        double ck = th * B[KORD][k] / 1024.0;         // theta_k * C(K,k)/2^K
        for (int j = 0; j <= KORD; j++) {
            double s = 0.0;
            for (int i = 0; i <= k; i++) {
                int l = j - i;
                if (l >= 0 && l <= KORD - k) {
                    double t = B[k][i] * B[KORD - k][l];
                    s += (i & 1) ? -t : t;
                }
            }
            a[j] += ck * s;
        }
    }
    for (int j = 0; j <= KORD; j++) g_coef[j] = (float)a[j];
}

// ---------------- fp16 tensor-core GEMM (mma.sync m16n8k16) ----------------
__device__ __forceinline__ void mma_f16(float* d, const uint32_t* a, const uint32_t* b) {
    asm volatile(
        "mma.sync.aligned.m16n8k16.row.col.f32.f16.f16.f32 "
        "{%0,%1,%2,%3}, {%4,%5,%6,%7}, {%8,%9}, {%0,%1,%2,%3};"
        : "+f"(d[0]), "+f"(d[1]), "+f"(d[2]), "+f"(d[3])
        : "r"(a[0]), "r"(a[1]), "r"(a[2]), "r"(a[3]), "r"(b[0]), "r"(b[1]));
}

// A: [M,Kd] row-major (fp32 if AF32, converted inline; else fp16).
// Bt: [Nd,Kd] fp16 (pre-transposed). C = relu?(A@B + bias).
// WF: write fp32 C ; WH: write fp16 copy to Ch.
template <int BM, int BN, int WM, int WN, bool AF32, bool RELU, bool WF, bool WH>
__launch_bounds__(256)
__global__ void gemm_h_k(const void* __restrict__ Ain, const __half* __restrict__ Bt,
                         const float* __restrict__ bias, float* __restrict__ C,
                         __half2* __restrict__ Ch, int M, int Kd, int Nd) {
    constexpr int BK = 32;
    constexpr int APITCH = BK + 8;                 // halves
    constexpr int BPITCH = BK + 8;
    constexpr int WTM = BM / WM;
    constexpr int WTN = BN / WN;
    constexpr int MT = WTM / 16;
    constexpr int NT = WTN / 8;
    constexpr int AV4 = (BM * BK) / (256 * 4);     // fp32 A: float4 loads / thread
    constexpr int AVH = (BM * BK) / (256 * 8);     // fp16 A: uint4 loads / thread
    constexpr int BV  = (BN * BK) / (256 * 8);     // fp16 B: uint4 loads / thread

    __shared__ __align__(16) __half As[BM * APITCH];
    __shared__ __align__(16) __half Bs[BN * BPITCH];

    const float*  Af = (const float*)Ain;
    const __half* Ah = (const __half*)Ain;

    const int tid  = threadIdx.x;
    const int lane = tid & 31;
    const int w    = tid >> 5;
    const int wm   = w % WM;
    const int wn   = w / WM;
    const int m0   = blockIdx.y * BM;
    const int n0   = blockIdx.x * BN;

    float acc[MT][NT][4];
#pragma unroll
    for (int i = 0; i < MT; i++)
#pragma unroll
        for (int j = 0; j < NT; j++)
#pragma unroll
            for (int q = 0; q < 4; q++) acc[i][j][q] = 0.0f;

    float4 aSf[AF32 ? AV4 : 1];
    uint4  aSh[AF32 ? 1 : AVH];
    uint4  bS[BV];

    // prefetch tile 0
    if (AF32) {
#pragma unroll
        for (int i = 0; i < AV4; i++) {
            int idx = tid + i * 256;
            int r = idx >> 3, c = (idx & 7) * 4;
            int gm = min(m0 + r, M - 1);
            aSf[i] = *reinterpret_cast<const float4*>(&Af[(size_t)gm * Kd + c]);
        }
    } else {
#pragma unroll
        for (int i = 0; i < AVH; i++) {
            int idx = tid + i * 256;
            int r = idx >> 2, c = (idx & 3) * 8;
            int gm = min(m0 + r, M - 1);
            aSh[i] = *reinterpret_cast<const uint4*>(&Ah[(size_t)gm * Kd + c]);
        }
    }
#pragma unroll
    for (int i = 0; i < BV; i++) {
        int idx = tid + i * 256;
        int n = idx >> 2, kg = (idx & 3) * 8;
        bS[i] = *reinterpret_cast<const uint4*>(&Bt[(size_t)(n0 + n) * Kd + kg]);
    }

    for (int kt = 0; kt < Kd; kt += BK) {
        // stage regs -> smem
        if (AF32) {
#pragma unroll
            for (int i = 0; i < AV4; i++) {
                int idx = tid + i * 256;
                int r = idx >> 3, c = (idx & 7) * 4;
                __half2 lo = __floats2half2_rn(aSf[i].x, aSf[i].y);
                __half2 hi = __floats2half2_rn(aSf[i].z, aSf[i].w);
                *reinterpret_cast<uint2*>(&As[r * APITCH + c]) =
                    make_uint2(*(uint32_t*)&lo, *(uint32_t*)&hi);
            }
        } else {
#pragma unroll
            for (int i = 0; i < AVH; i++) {
                int idx = tid + i * 256;
                int r = idx >> 2, c = (idx & 3) * 8;
                *reinterpret_cast<uint4*>(&As[r * APITCH + c]) = aSh[i];
            }
        }
#pragma unroll
        for (int i = 0; i < BV; i++) {
            int idx = tid + i * 256;
            int n = idx >> 2, kg = (idx & 3) * 8;
            *reinterpret_cast<uint4*>(&Bs[n * BPITCH + kg]) = bS[i];
        }
        __syncthreads();

        // prefetch next tile
        if (kt + BK < Kd) {
            if (AF32) {
#pragma unroll
                for (int i = 0; i < AV4; i++) {
                    int idx = tid + i * 256;
                    int r = idx >> 3, c = (idx & 7) * 4;
                    int gm = min(m0 + r, M - 1);
                    aSf[i] = *reinterpret_cast<const float4*>(&Af[(size_t)gm * Kd + kt + BK + c]);
                }
            } else {
#pragma unroll
                for (int i = 0; i < AVH; i++) {
                    int idx = tid + i * 256;
                    int r = idx >> 2, c = (idx & 3) * 8;
                    int gm = min(m0 + r, M - 1);
                    aSh[i] = *reinterpret_cast<const uint4*>(&Ah[(size_t)gm * Kd + kt + BK + c]);
                }
            }
#pragma unroll
            for (int i = 0; i < BV; i++) {
                int idx = tid + i * 256;
                int n = idx >> 2, kg = (idx & 3) * 8;
                bS[i] = *reinterpret_cast<const uint4*>(&Bt[(size_t)(n0 + n) * Kd + kt + BK + kg]);
            }
        }

        // compute: 2 chunks of k16
#pragma unroll
        for (int ch = 0; ch < 2; ch++) {
            const int c0 = ch * 16 + (lane & 3) * 2;
            uint32_t afr[MT][4], bfr[NT][2];
#pragma unroll
            for (int mt = 0; mt < MT; mt++) {
                int r = wm * WTM + mt * 16 + (lane >> 2);
                afr[mt][0] = *reinterpret_cast<const uint32_t*>(&As[r * APITCH + c0]);
                afr[mt][1] = *reinterpret_cast<const uint32_t*>(&As[(r + 8) * APITCH + c0]);
                afr[mt][2] = *reinterpret_cast<const uint32_t*>(&As[r * APITCH + c0 + 8]);
                afr[mt][3] = *reinterpret_cast<const uint32_t*>(&As[(r + 8) * APITCH + c0 + 8]);
            }
#pragma unroll
            for (int nt = 0; nt < NT; nt++) {
                int n = wn * WTN + nt * 8 + (lane >> 2);
                bfr[nt][0] = *reinterpret_cast<const uint32_t*>(&Bs[n * BPITCH + c0]);
                bfr[nt][1] = *reinterpret_cast<const uint32_t*>(&Bs[n * BPITCH + c0 + 8]);
            }
#pragma unroll
            for (int mt = 0; mt < MT; mt++)
#pragma unroll
                for (int nt = 0; nt < NT; nt++)
                    mma_f16(acc[mt][nt], afr[mt], bfr[nt]);
        }
        __syncthreads();
    }

    // epilogue: bias (+relu)
#pragma unroll
    for (int mt = 0; mt < MT; mt++) {
#pragma unroll
        for (int nt = 0; nt < NT; nt++) {
            int col = n0 + wn * WTN + nt * 8 + (lane & 3) * 2;
            float bx = bias[col], by = bias[col + 1];
            int r0 = m0 + wm * WTM + mt * 16 + (lane >> 2);
            float vx = acc[mt][nt][0] + bx;
            float vy = acc[mt][nt][1] + by;
            if (RELU) { vx = fmaxf(vx, 0.0f); vy = fmaxf(vy, 0.0f); }
            if (r0 < M) {
                if (WF) *reinterpret_cast<float2*>(&C[(size_t)r0 * Nd + col]) = make_float2(vx, vy);
                if (WH) Ch[((size_t)r0 * Nd + col) >> 1] = __floats2half2_rn(vx, vy);
            }
            int r1 = r0 + 8;
            vx = acc[mt][nt][2] + bx;
            vy = acc[mt][nt][3] + by;
            if (RELU) { vx = fmaxf(vx, 0.0f); vy = fmaxf(vy, 0.0f); }
            if (r1 < M) {
                if (WF) *reinterpret_cast<float2*>(&C[(size_t)r1 * Nd + col]) = make_float2(vx, vy);
                if (WH) Ch[((size_t)r1 * Nd + col) >> 1] = __floats2half2_rn(vx, vy);
            }
        }
    }
}

// ---------------- Horner SpMV (fp16 gather, fp32 accumulate) ----------------
__device__ __forceinline__ void spmv_body(const __half2* __restrict__ vin,
                                          const float* __restrict__ h,
                                          int jadd, int jmul, int wid, int lane,
                                          float& accx, float& accy) {
    float aj = g_coef[jadd];
    float gm = (jmul >= 0) ? g_coef[jmul] : 1.0f;
    float2 hv = reinterpret_cast<const float2*>(h)[(size_t)wid * 32 + lane];
    accx = aj * hv.x;
    accy = aj * hv.y;
    int idx = g_start[wid];
    int e   = g_start[wid + 1];
    for (; idx + 16 <= e; idx += 16) {
        int2 ed[16];
        __half2 gv[16];
#pragma unroll
        for (int q = 0; q < 16; q++) ed[q] = g_edge[idx + q];
#pragma unroll
        for (int q = 0; q < 16; q++) gv[q] = vin[(size_t)ed[q].x * 32 + lane];
#pragma unroll
        for (int q = 0; q < 16; q++) {
            float w = gm * __int_as_float(ed[q].y);
            float2 f = __half22float2(gv[q]);
            accx = fmaf(w, f.x, accx);
            accy = fmaf(w, f.y, accy);
        }
    }
    for (; idx + 4 <= e; idx += 4) {
        int2 ed[4];
        __half2 gv[4];
#pragma unroll
        for (int q = 0; q < 4; q++) ed[q] = g_edge[idx + q];
#pragma unroll
        for (int q = 0; q < 4; q++) gv[q] = vin[(size_t)ed[q].x * 32 + lane];
#pragma unroll
        for (int q = 0; q < 4; q++) {
            float w = gm * __int_as_float(ed[q].y);
            float2 f = __half22float2(gv[q]);
            accx = fmaf(w, f.x, accx);
            accy = fmaf(w, f.y, accy);
        }
    }
    for (; idx < e; ++idx) {
        int2 ed = g_edge[idx];
        float w = gm * __int_as_float(ed.y);
        float2 f = __half22float2(vin[(size_t)ed.x * 32 + lane]);
        accx = fmaf(w, f.x, accx);
        accy = fmaf(w, f.y, accy);
    }
}

__launch_bounds__(256)
__global__ void spmv_h_k(const __half2* __restrict__ vin, __half2* __restrict__ vout,
                         const float* __restrict__ h, int jadd, int jmul) {
    int wid  = (blockIdx.x * blockDim.x + threadIdx.x) >> 5;
    int lane = threadIdx.x & 31;
    if (wid >= N_NODES) return;
    float accx, accy;
    spmv_body(vin, h, jadd, jmul, wid, lane, accx, accy);
    vout[(size_t)wid * 32 + lane] = __floats2half2_rn(accx, accy);
}

// final pass fused with log_softmax over the 64 classes (warp holds full row)
__launch_bounds__(256)
__global__ void spmv_lsm_k(const __half2* __restrict__ vin, float* __restrict__ out,
                           const float* __restrict__ h) {
    int wid  = (blockIdx.x * blockDim.x + threadIdx.x) >> 5;
    int lane = threadIdx.x & 31;
    if (wid >= N_NODES) return;
    float vx, vy;
    spmv_body(vin, h, 0, -1, wid, lane, vx, vy);
    float m = fmaxf(vx, vy);
#pragma unroll
    for (int o = 16; o; o >>= 1) m = fmaxf(m, __shfl_xor_sync(0xFFFFFFFFu, m, o));
    float s = expf(vx - m) + expf(vy - m);
#pragma unroll
    for (int o = 16; o; o >>= 1) s += __shfl_xor_sync(0xFFFFFFFFu, s, o);
    float l = m + logf(s);
    reinterpret_cast<float2*>(out)[(size_t)wid * 32 + lane] = make_float2(vx - l, vy - l);
}

// ---------------- launcher ----------------
extern "C" void kernel_launch(void* const* d_in, const int* in_sizes, int n_in,
                              void* d_out, int out_size) {
    const float* x    = (const float*)d_in[0];
    const int*   ei   = (const int*)  d_in[1];
    const float* W1   = (const float*)d_in[2];
    const float* b1   = (const float*)d_in[3];
    const float* W2   = (const float*)d_in[4];
    const float* b2   = (const float*)d_in[5];
    const float* temp = (const float*)d_in[6];
    float*       out  = (float*)d_out;
    const int* row = ei;
    const int* col = ei + N_EDGES;

    float *ph;
    __half *pw1h, *pw2h, *ph1h;
    __half2 *phh, *pq0, *pq1;
    cudaGetSymbolAddress((void**)&pw1h, g_w1h);
    cudaGetSymbolAddress((void**)&pw2h, g_w2h);
    cudaGetSymbolAddress((void**)&ph1h, g_h1h);
    cudaGetSymbolAddress((void**)&ph,   g_h);
    cudaGetSymbolAddress((void**)&phh,  g_hh);
    cudaGetSymbolAddress((void**)&pq0,  g_q0);
    cudaGetSymbolAddress((void**)&pq1,  g_q1);

    // side stream + events for branch parallelism inside the captured graph
    // (created once; host-side resources only — no device memory)
    static cudaStream_t s2 = nullptr;
    static cudaEvent_t  evF = nullptr, evJ = nullptr;
    if (s2 == nullptr) {
        cudaStreamCreateWithFlags(&s2, cudaStreamNonBlocking);
        cudaEventCreateWithFlags(&evF, cudaEventDisableTiming);
        cudaEventCreateWithFlags(&evJ, cudaEventDisableTiming);
    }

    // fork: CSR chain on s2, MLP on main stream
    cudaEventRecord(evF, 0);
    cudaStreamWaitEvent(s2, evF, 0);

    // --- branch A (s2): CSR build ---
    zero_cnt_k<<<(N_NODES + 255) / 256, 256, 0, s2>>>();
    hist_k<<<(N_EDGES / 2 + 255) / 256, 256, 0, s2>>>(row);
    scanA_k<<<NSCAN_BLOCKS, 256, 0, s2>>>();
    scanB_k<<<1, 128, 0, s2>>>();
    scanC_k<<<NSCAN_BLOCKS, 256, 0, s2>>>();
    scatter_k<<<(N_EDGES / 2 + 255) / 256, 256, 0, s2>>>(row, col);

    // --- branch B (main): weights, MLP, coefficients ---
    convW_k<<<(D_IN * D_HID + D_HID * D_OUT + 255) / 256, 256>>>(W1, W2);
    {
        // GEMM1: 128x64 tile (32 accum regs/thread -> higher occupancy)
        dim3 g1(D_HID / 64, (N_NODES + 127) / 128);
        gemm_h_k<128, 64, 4, 2, true, true, false, true>
            <<<g1, 256>>>(x, pw1h, b1, nullptr, (__half2*)ph1h, N_NODES, D_IN, D_HID);
    }
    coef_k<<<1, 32>>>(temp);
    {
        dim3 g2(D_OUT / 64, (N_NODES + 127) / 128);
        gemm_h_k<128, 64, 4, 2, false, false, true, true>
            <<<g2, 256>>>(ph1h, pw2h, b2, ph, phh, N_NODES, D_HID, D_OUT);
    }

    // join: SpMV chain needs both CSR and h
    cudaEventRecord(evJ, s2);
    cudaStreamWaitEvent(0, evJ, 0);

    // Horner evaluation: r = aK*h; then r = A r + a_j h, j = K-1 .. 0
    const int warp_blocks = (N_NODES * 32 + 255) / 256;
    spmv_h_k<<<warp_blocks, 256>>>(phh, pq0, ph, KORD - 1, KORD);
    __half2* qcur = pq0;
    __half2* qnxt = pq1;
    for (int j = KORD - 2; j >= 1; j--) {
        spmv_h_k<<<warp_blocks, 256>>>(qcur, qnxt, ph, j, -1);
        __half2* t = qcur; qcur = qnxt; qnxt = t;
    }
    // last pass fused with log_softmax
    spmv_lsm_k<<<warp_blocks, 256>>>(qcur, out, ph);
}

// round 14
// speedup vs baseline: 3.2864x; 3.2864x over previous
#include <cuda_runtime.h>
#include <cuda_fp16.h>
#include <math.h>
#include <stdint.h>

#define N_NODES 100000
#define N_EDGES 3200000
#define D_IN    512
#define D_HID   256
#define D_OUT   64
#define KORD    10

#define SCAN_CHUNK   1024
#define NSCAN_BLOCKS ((N_NODES + SCAN_CHUNK - 1) / SCAN_CHUNK)   // 98

// ---------------- device scratch (no allocations allowed) ----------------
__device__ int     g_cnt[N_NODES];
__device__ int     g_pos[N_NODES];
__device__ int     g_start[N_NODES + 1];
__device__ float   g_dinv[N_NODES];
__device__ int     g_bsum[NSCAN_BLOCKS];
__device__ int     g_boff[NSCAN_BLOCKS];
__device__ int2    g_edge[N_EDGES];                        // (col, w bits) CSR by row
__device__ __half  g_w1h[(size_t)D_HID * D_IN];            // W1^T fp16 [256][512]
__device__ __half  g_w2h[(size_t)D_OUT * D_HID];           // W2^T fp16 [64][256]
__device__ __half  g_h1h[(size_t)N_NODES * D_HID];         // MLP hidden fp16
__device__ float   g_h [(size_t)N_NODES * D_OUT];          // MLP output fp32
__device__ __half2 g_hh[(size_t)N_NODES * (D_OUT / 2)];    // MLP output fp16
__device__ __half2 g_q0[(size_t)N_NODES * (D_OUT / 2)];    // Horner intermediates (fp16)
__device__ __half2 g_q1[(size_t)N_NODES * (D_OUT / 2)];
__device__ float   g_coef[KORD + 1];                       // monomial coeffs of poly in A
__device__ int     g_deg;                                  // true polynomial degree

// ---------------- Bernstein -> monomial coefficients (exact in double) ----------------
// Also computes the exact polynomial degree d = max{j : a_j != 0}. The binomial
// convolutions are integer-valued and exact in double; /1024 is a power of two,
// so a_j == 0.0 tests are exact (no threshold needed).
__global__ void coef_k(const float* __restrict__ temp) {
    if (threadIdx.x != 0 || blockIdx.x != 0) return;
    double B[KORD + 1][KORD + 1];
    for (int n = 0; n <= KORD; n++) {
        for (int j = 0; j <= KORD; j++) B[n][j] = 0.0;
        B[n][0] = 1.0;
        for (int j = 1; j <= n; j++)
            B[n][j] = (j == n) ? 1.0 : (B[n - 1][j - 1] + B[n - 1][j]);
    }
    double a[KORD + 1];
    for (int j = 0; j <= KORD; j++) a[j] = 0.0;
    for (int k = 0; k <= KORD; k++) {
        double th = (double)temp[k];
        if (th < 0.0) th = 0.0;                       // relu
        double ck = th * B[KORD][k] / 1024.0;         // theta_k * C(K,k)/2^K
        for (int j = 0; j <= KORD; j++) {
            double s = 0.0;
            for (int i = 0; i <= k; i++) {
                int l = j - i;
                if (l >= 0 && l <= KORD - k) {
                    double t = B[k][i] * B[KORD - k][l];
                    s += (i & 1) ? -t : t;
                }
            }
            a[j] += ck * s;
        }
    }
    int d = 0;
    for (int j = 0; j <= KORD; j++) {
        g_coef[j] = (float)a[j];
        if (a[j] != 0.0) d = j;
    }
    g_deg = d;
}

// ---------------- CSR build (skipped entirely when degree == 0) ----------------
__global__ void zero_cnt_k() {
    if (g_deg == 0) return;
    int i = blockIdx.x * blockDim.x + threadIdx.x;
    if (i < N_NODES) g_cnt[i] = 0;
}

// 2 edges per thread
__global__ void hist_k(const int* __restrict__ row) {
    if (g_deg == 0) return;
    int t = blockIdx.x * blockDim.x + threadIdx.x;
    int e0 = t * 2;
    if (e0 >= N_EDGES) return;
    int2 r2 = *reinterpret_cast<const int2*>(&row[e0]);
    atomicAdd(&g_cnt[r2.x], 1);
    atomicAdd(&g_cnt[r2.y], 1);
}

// --- multi-block exclusive scan over g_cnt ---
__global__ void scanA_k() {
    if (g_deg == 0) return;
    __shared__ int ws[8];
    int b    = blockIdx.x;
    int tid  = threadIdx.x;
    int lane = tid & 31, warp = tid >> 5;
    int base = b * SCAN_CHUNK + tid * 4;
    int s = 0;
#pragma unroll
    for (int q = 0; q < 4; q++) {
        int i = base + q;
        if (i < N_NODES) s += g_cnt[i];
    }
#pragma unroll
    for (int o = 16; o; o >>= 1) s += __shfl_xor_sync(0xFFFFFFFFu, s, o);
    if (lane == 0) ws[warp] = s;
    __syncthreads();
    if (tid == 0) {
        int t = 0;
#pragma unroll
        for (int q = 0; q < 8; q++) t += ws[q];
        g_bsum[b] = t;
    }
}

__global__ void scanB_k() {
    if (g_deg == 0) return;
    __shared__ int ws[4];
    int tid = threadIdx.x, lane = tid & 31, warp = tid >> 5;   // 128 threads
    int v = (tid < NSCAN_BLOCKS) ? g_bsum[tid] : 0;
    int incl = v;
#pragma unroll
    for (int o = 1; o < 32; o <<= 1) {
        int t = __shfl_up_sync(0xFFFFFFFFu, incl, o);
        if (lane >= o) incl += t;
    }
    if (lane == 31) ws[warp] = incl;
    __syncthreads();
    if (warp == 0 && lane < 4) {
        int w = ws[lane];
#pragma unroll
        for (int o = 1; o < 4; o <<= 1) {
            int t = __shfl_up_sync(0xFu, w, o);
            if (lane >= o) w += t;
        }
        ws[lane] = w;
    }
    __syncthreads();
    int woff = (warp > 0) ? ws[warp - 1] : 0;
    if (tid < NSCAN_BLOCKS) g_boff[tid] = woff + incl - v;
    if (tid == 0) g_start[N_NODES] = N_EDGES;
}

__global__ void scanC_k() {
    if (g_deg == 0) return;
    __shared__ int ws[8];
    int b    = blockIdx.x;
    int tid  = threadIdx.x;
    int lane = tid & 31, warp = tid >> 5;
    int base = b * SCAN_CHUNK + tid * 4;
    int v[4];
    int ts = 0;
#pragma unroll
    for (int q = 0; q < 4; q++) {
        int i = base + q;
        v[q] = (i < N_NODES) ? g_cnt[i] : 0;
        ts += v[q];
    }
    int incl = ts;
#pragma unroll
    for (int o = 1; o < 32; o <<= 1) {
        int t = __shfl_up_sync(0xFFFFFFFFu, incl, o);
        if (lane >= o) incl += t;
    }
    if (lane == 31) ws[warp] = incl;
    __syncthreads();
    if (warp == 0 && lane < 8) {
        int w = ws[lane];
#pragma unroll
        for (int o = 1; o < 8; o <<= 1) {
            int t = __shfl_up_sync(0xFFu, w, o);
            if (lane >= o) w += t;
        }
        ws[lane] = w;
    }
    __syncthreads();
    int off = g_boff[b] + ((warp > 0) ? ws[warp - 1] : 0) + (incl - ts);
#pragma unroll
    for (int q = 0; q < 4; q++) {
        int i = base + q;
        if (i < N_NODES) {
            g_start[i] = off;
            g_pos[i]   = off;
            g_dinv[i]  = (v[q] > 0) ? rsqrtf((float)v[q]) : 0.0f;
        }
        off += v[q];
    }
}

// 2 edges per thread
__global__ void scatter_k(const int* __restrict__ row, const int* __restrict__ col) {
    if (g_deg == 0) return;
    int t = blockIdx.x * blockDim.x + threadIdx.x;
    int e0 = t * 2;
    if (e0 >= N_EDGES) return;
    int2 r2 = *reinterpret_cast<const int2*>(&row[e0]);
    int2 c2 = *reinterpret_cast<const int2*>(&col[e0]);
    int p0 = atomicAdd(&g_pos[r2.x], 1);
    g_edge[p0] = make_int2(c2.x, __float_as_int(g_dinv[r2.x] * g_dinv[c2.x]));
    int p1 = atomicAdd(&g_pos[r2.y], 1);
    g_edge[p1] = make_int2(c2.y, __float_as_int(g_dinv[r2.y] * g_dinv[c2.y]));
}

// ---------------- W1/W2 -> fp16 transposed ----------------
__global__ void convW_k(const float* __restrict__ W1, const float* __restrict__ W2) {
    int i = blockIdx.x * blockDim.x + threadIdx.x;
    if (i < D_IN * D_HID) {
        int k = i / D_HID, n = i % D_HID;          // W1[k][n]
        g_w1h[(size_t)n * D_IN + k] = __float2half_rn(W1[i]);
    }
    int j = i - D_IN * D_HID;
    if (j >= 0 && j < D_HID * D_OUT) {
        int k = j / D_OUT, n = j % D_OUT;          // W2[k][n]
        g_w2h[(size_t)n * D_HID + k] = __float2half_rn(W2[j]);
    }
}

// ---------------- fp16 tensor-core GEMM (mma.sync m16n8k16) ----------------
__device__ __forceinline__ void mma_f16(float* d, const uint32_t* a, const uint32_t* b) {
    asm volatile(
        "mma.sync.aligned.m16n8k16.row.col.f32.f16.f16.f32 "
        "{%0,%1,%2,%3}, {%4,%5,%6,%7}, {%8,%9}, {%0,%1,%2,%3};"
        : "+f"(d[0]), "+f"(d[1]), "+f"(d[2]), "+f"(d[3])
        : "r"(a[0]), "r"(a[1]), "r"(a[2]), "r"(a[3]), "r"(b[0]), "r"(b[1]));
}

// A: [M,Kd] row-major (fp32 if AF32, converted inline; else fp16).
// Bt: [Nd,Kd] fp16 (pre-transposed). C = relu?(A@B + bias).
// WF: write fp32 C ; WH: write fp16 copy to Ch.
template <int BM, int BN, int WM, int WN, bool AF32, bool RELU, bool WF, bool WH>
__launch_bounds__(256)
__global__ void gemm_h_k(const void* __restrict__ Ain, const __half* __restrict__ Bt,
                         const float* __restrict__ bias, float* __restrict__ C,
                         __half2* __restrict__ Ch, int M, int Kd, int Nd) {
    constexpr int BK = 32;
    constexpr int APITCH = BK + 8;                 // halves
    constexpr int BPITCH = BK + 8;
    constexpr int WTM = BM / WM;
    constexpr int WTN = BN / WN;
    constexpr int MT = WTM / 16;
    constexpr int NT = WTN / 8;
    constexpr int AV4 = (BM * BK) / (256 * 4);     // fp32 A: float4 loads / thread
    constexpr int AVH = (BM * BK) / (256 * 8);     // fp16 A: uint4 loads / thread
    constexpr int BV  = (BN * BK) / (256 * 8);     // fp16 B: uint4 loads / thread

    __shared__ __align__(16) __half As[BM * APITCH];
    __shared__ __align__(16) __half Bs[BN * BPITCH];

    const float*  Af = (const float*)Ain;
    const __half* Ah = (const __half*)Ain;

    const int tid  = threadIdx.x;
    const int lane = tid & 31;
    const int w    = tid >> 5;
    const int wm   = w % WM;
    const int wn   = w / WM;
    const int m0   = blockIdx.y * BM;
    const int n0   = blockIdx.x * BN;

    float acc[MT][NT][4];
#pragma unroll
    for (int i = 0; i < MT; i++)
#pragma unroll
        for (int j = 0; j < NT; j++)
#pragma unroll
            for (int q = 0; q < 4; q++) acc[i][j][q] = 0.0f;

    float4 aSf[AF32 ? AV4 : 1];
    uint4  aSh[AF32 ? 1 : AVH];
    uint4  bS[BV];

    // prefetch tile 0
    if (AF32) {
#pragma unroll
        for (int i = 0; i < AV4; i++) {
            int idx = tid + i * 256;
            int r = idx >> 3, c = (idx & 7) * 4;
            int gm = min(m0 + r, M - 1);
            aSf[i] = *reinterpret_cast<const float4*>(&Af[(size_t)gm * Kd + c]);
        }
    } else {
#pragma unroll
        for (int i = 0; i < AVH; i++) {
            int idx = tid + i * 256;
            int r = idx >> 2, c = (idx & 3) * 8;
            int gm = min(m0 + r, M - 1);
            aSh[i] = *reinterpret_cast<const uint4*>(&Ah[(size_t)gm * Kd + c]);
        }
    }
#pragma unroll
    for (int i = 0; i < BV; i++) {
        int idx = tid + i * 256;
        int n = idx >> 2, kg = (idx & 3) * 8;
        bS[i] = *reinterpret_cast<const uint4*>(&Bt[(size_t)(n0 + n) * Kd + kg]);
    }

    for (int kt = 0; kt < Kd; kt += BK) {
        // stage regs -> smem
        if (AF32) {
#pragma unroll
            for (int i = 0; i < AV4; i++) {
                int idx = tid + i * 256;
                int r = idx >> 3, c = (idx & 7) * 4;
                __half2 lo = __floats2half2_rn(aSf[i].x, aSf[i].y);
                __half2 hi = __floats2half2_rn(aSf[i].z, aSf[i].w);
                *reinterpret_cast<uint2*>(&As[r * APITCH + c]) =
                    make_uint2(*(uint32_t*)&lo, *(uint32_t*)&hi);
            }
        } else {
#pragma unroll
            for (int i = 0; i < AVH; i++) {
                int idx = tid + i * 256;
                int r = idx >> 2, c = (idx & 3) * 8;
                *reinterpret_cast<uint4*>(&As[r * APITCH + c]) = aSh[i];
            }
        }
#pragma unroll
        for (int i = 0; i < BV; i++) {
            int idx = tid + i * 256;
            int n = idx >> 2, kg = (idx & 3) * 8;
            *reinterpret_cast<uint4*>(&Bs[n * BPITCH + kg]) = bS[i];
        }
        __syncthreads();

        // prefetch next tile
        if (kt + BK < Kd) {
            if (AF32) {
#pragma unroll
                for (int i = 0; i < AV4; i++) {
                    int idx = tid + i * 256;
                    int r = idx >> 3, c = (idx & 7) * 4;
                    int gm = min(m0 + r, M - 1);
                    aSf[i] = *reinterpret_cast<const float4*>(&Af[(size_t)gm * Kd + kt + BK + c]);
                }
            } else {
#pragma unroll
                for (int i = 0; i < AVH; i++) {
                    int idx = tid + i * 256;
                    int r = idx >> 2, c = (idx & 3) * 8;
                    int gm = min(m0 + r, M - 1);
                    aSh[i] = *reinterpret_cast<const uint4*>(&Ah[(size_t)gm * Kd + kt + BK + c]);
                }
            }
#pragma unroll
            for (int i = 0; i < BV; i++) {
                int idx = tid + i * 256;
                int n = idx >> 2, kg = (idx & 3) * 8;
                bS[i] = *reinterpret_cast<const uint4*>(&Bt[(size_t)(n0 + n) * Kd + kt + BK + kg]);
            }
        }

        // compute: 2 chunks of k16
#pragma unroll
        for (int ch = 0; ch < 2; ch++) {
            const int c0 = ch * 16 + (lane & 3) * 2;
            uint32_t afr[MT][4], bfr[NT][2];
#pragma unroll
            for (int mt = 0; mt < MT; mt++) {
                int r = wm * WTM + mt * 16 + (lane >> 2);
                afr[mt][0] = *reinterpret_cast<const uint32_t*>(&As[r * APITCH + c0]);
                afr[mt][1] = *reinterpret_cast<const uint32_t*>(&As[(r + 8) * APITCH + c0]);
                afr[mt][2] = *reinterpret_cast<const uint32_t*>(&As[r * APITCH + c0 + 8]);
                afr[mt][3] = *reinterpret_cast<const uint32_t*>(&As[(r + 8) * APITCH + c0 + 8]);
            }
#pragma unroll
            for (int nt = 0; nt < NT; nt++) {
                int n = wn * WTN + nt * 8 + (lane >> 2);
                bfr[nt][0] = *reinterpret_cast<const uint32_t*>(&Bs[n * BPITCH + c0]);
                bfr[nt][1] = *reinterpret_cast<const uint32_t*>(&Bs[n * BPITCH + c0 + 8]);
            }
#pragma unroll
            for (int mt = 0; mt < MT; mt++)
#pragma unroll
                for (int nt = 0; nt < NT; nt++)
                    mma_f16(acc[mt][nt], afr[mt], bfr[nt]);
        }
        __syncthreads();
    }

    // epilogue: bias (+relu)
#pragma unroll
    for (int mt = 0; mt < MT; mt++) {
#pragma unroll
        for (int nt = 0; nt < NT; nt++) {
            int col = n0 + wn * WTN + nt * 8 + (lane & 3) * 2;
            float bx = bias[col], by = bias[col + 1];
            int r0 = m0 + wm * WTM + mt * 16 + (lane >> 2);
            float vx = acc[mt][nt][0] + bx;
            float vy = acc[mt][nt][1] + by;
            if (RELU) { vx = fmaxf(vx, 0.0f); vy = fmaxf(vy, 0.0f); }
            if (r0 < M) {
                if (WF) *reinterpret_cast<float2*>(&C[(size_t)r0 * Nd + col]) = make_float2(vx, vy);
                if (WH) Ch[((size_t)r0 * Nd + col) >> 1] = __floats2half2_rn(vx, vy);
            }
            int r1 = r0 + 8;
            vx = acc[mt][nt][2] + bx;
            vy = acc[mt][nt][3] + by;
            if (RELU) { vx = fmaxf(vx, 0.0f); vy = fmaxf(vy, 0.0f); }
            if (r1 < M) {
                if (WF) *reinterpret_cast<float2*>(&C[(size_t)r1 * Nd + col]) = make_float2(vx, vy);
                if (WH) Ch[((size_t)r1 * Nd + col) >> 1] = __floats2half2_rn(vx, vy);
            }
        }
    }
}

// ---------------- Horner SpMV (fp16 gather, fp32 accumulate) ----------------
__device__ __forceinline__ void spmv_body(const __half2* __restrict__ vin,
                                          const float* __restrict__ h,
                                          int jadd, float gm, int wid, int lane,
                                          float& accx, float& accy) {
    float aj = g_coef[jadd];
    float2 hv = reinterpret_cast<const float2*>(h)[(size_t)wid * 32 + lane];
    accx = aj * hv.x;
    accy = aj * hv.y;
    int idx = g_start[wid];
    int e   = g_start[wid + 1];
    for (; idx + 16 <= e; idx += 16) {
        int2 ed[16];
        __half2 gv[16];
#pragma unroll
        for (int q = 0; q < 16; q++) ed[q] = g_edge[idx + q];
#pragma unroll
        for (int q = 0; q < 16; q++) gv[q] = vin[(size_t)ed[q].x * 32 + lane];
#pragma unroll
        for (int q = 0; q < 16; q++) {
            float w = gm * __int_as_float(ed[q].y);
            float2 f = __half22float2(gv[q]);
            accx = fmaf(w, f.x, accx);
            accy = fmaf(w, f.y, accy);
        }
    }
    for (; idx + 4 <= e; idx += 4) {
        int2 ed[4];
        __half2 gv[4];
#pragma unroll
        for (int q = 0; q < 4; q++) ed[q] = g_edge[idx + q];
#pragma unroll
        for (int q = 0; q < 4; q++) gv[q] = vin[(size_t)ed[q].x * 32 + lane];
#pragma unroll
        for (int q = 0; q < 4; q++) {
            float w = gm * __int_as_float(ed[q].y);
            float2 f = __half22float2(gv[q]);
            accx = fmaf(w, f.x, accx);
            accy = fmaf(w, f.y, accy);
        }
    }
    for (; idx < e; ++idx) {
        int2 ed = g_edge[idx];
        float w = gm * __int_as_float(ed.y);
        float2 f = __half22float2(vin[(size_t)ed.x * 32 + lane]);
        accx = fmaf(w, f.x, accx);
        accy = fmaf(w, f.y, accy);
    }
}

// Adaptive-degree Horner pass for coefficient index jpass (K-1 .. 1):
//   jpass > d : upstream coefficients all zero -> no-op
//   jpass == d: vout = a_d * h  (flat scaled copy from hh; no gather)
//   jpass < d : vout = A_hat * vin + a_jpass * h (vin = hh with gm=a_K on first pass)
__launch_bounds__(256)
__global__ void spmv_h_k(const __half2* __restrict__ vin, __half2* __restrict__ vout,
                         const __half2* __restrict__ hh, const float* __restrict__ h,
                         int jpass) {
    int d = g_deg;
    if (jpass > d) return;
    int gidx = blockIdx.x * blockDim.x + threadIdx.x;
    if (jpass == d) {
        // flat scaled copy: vout = a_d * h (from fp16 h copy)
        if (gidx < N_NODES * 32) {
            float a = g_coef[d];
            float2 f = __half22float2(hh[gidx]);
            vout[gidx] = __floats2half2_rn(a * f.x, a * f.y);
        }
        return;
    }
    int wid  = gidx >> 5;
    int lane = threadIdx.x & 31;
    if (wid >= N_NODES) return;
    bool first = (jpass == KORD - 1);          // only reachable when d == KORD
    const __half2* vsrc = first ? hh : vin;
    float gm = first ? g_coef[KORD] : 1.0f;
    float accx, accy;
    spmv_body(vsrc, h, jpass, gm, wid, lane, accx, accy);
    vout[(size_t)wid * 32 + lane] = __floats2half2_rn(accx, accy);
}

// final pass (j = 0) fused with log_softmax; skips the gather entirely when d == 0
__launch_bounds__(256)
__global__ void spmv_lsm_k(const __half2* __restrict__ vin, float* __restrict__ out,
                           const float* __restrict__ h) {
    int wid  = (blockIdx.x * blockDim.x + threadIdx.x) >> 5;
    int lane = threadIdx.x & 31;
    if (wid >= N_NODES) return;
    float vx, vy;
    if (g_deg == 0) {
        float a0 = g_coef[0];
        float2 hv = reinterpret_cast<const float2*>(h)[(size_t)wid * 32 + lane];
        vx = a0 * hv.x;
        vy = a0 * hv.y;
    } else {
        spmv_body(vin, h, 0, 1.0f, wid, lane, vx, vy);
    }
    float m = fmaxf(vx, vy);
#pragma unroll
    for (int o = 16; o; o >>= 1) m = fmaxf(m, __shfl_xor_sync(0xFFFFFFFFu, m, o));
    float s = expf(vx - m) + expf(vy - m);
#pragma unroll
    for (int o = 16; o; o >>= 1) s += __shfl_xor_sync(0xFFFFFFFFu, s, o);
    float l = m + logf(s);
    reinterpret_cast<float2*>(out)[(size_t)wid * 32 + lane] = make_float2(vx - l, vy - l);
}

// ---------------- launcher ----------------
extern "C" void kernel_launch(void* const* d_in, const int* in_sizes, int n_in,
                              void* d_out, int out_size) {
    const float* x    = (const float*)d_in[0];
    const int*   ei   = (const int*)  d_in[1];
    const float* W1   = (const float*)d_in[2];
    const float* b1   = (const float*)d_in[3];
    const float* W2   = (const float*)d_in[4];
    const float* b2   = (const float*)d_in[5];
    const float* temp = (const float*)d_in[6];
    float*       out  = (float*)d_out;
    const int* row = ei;
    const int* col = ei + N_EDGES;

    float *ph;
    __half *pw1h, *pw2h, *ph1h;
    __half2 *phh, *pq0, *pq1;
    cudaGetSymbolAddress((void**)&pw1h, g_w1h);
    cudaGetSymbolAddress((void**)&pw2h, g_w2h);
    cudaGetSymbolAddress((void**)&ph1h, g_h1h);
    cudaGetSymbolAddress((void**)&ph,   g_h);
    cudaGetSymbolAddress((void**)&phh,  g_hh);
    cudaGetSymbolAddress((void**)&pq0,  g_q0);
    cudaGetSymbolAddress((void**)&pq1,  g_q1);

    // 1-3: weight conversion, coefficients (+degree), cnt zero
    convW_k<<<(D_IN * D_HID + D_HID * D_OUT + 255) / 256, 256>>>(W1, W2);
    coef_k<<<1, 32>>>(temp);
    zero_cnt_k<<<(N_NODES + 255) / 256, 256>>>();

    // 4: GEMM1 (128x128 tile — best measured config; ncu target slot)
    {
        dim3 g1(D_HID / 128, (N_NODES + 127) / 128);
        gemm_h_k<128, 128, 2, 4, true, true, false, true>
            <<<g1, 256>>>(x, pw1h, b1, nullptr, (__half2*)ph1h, N_NODES, D_IN, D_HID);
    }

    // CSR build (every kernel early-exits when degree == 0)
    hist_k<<<(N_EDGES / 2 + 255) / 256, 256>>>(row);
    scanA_k<<<NSCAN_BLOCKS, 256>>>();
    scanB_k<<<1, 128>>>();
    scanC_k<<<NSCAN_BLOCKS, 256>>>();
    scatter_k<<<(N_EDGES / 2 + 255) / 256, 256>>>(row, col);

    // GEMM2 (fp16 in, fp32 + fp16 out)
    {
        dim3 g2(D_OUT / 64, (N_NODES + 127) / 128);
        gemm_h_k<128, 64, 4, 2, false, false, true, true>
            <<<g2, 256>>>(ph1h, pw2h, b2, ph, phh, N_NODES, D_HID, D_OUT);
    }

    // Adaptive-degree Horner: passes j = K-1 .. 1, then fused lsm pass (j = 0)
    const int warp_blocks = (N_NODES * 32 + 255) / 256;
    __half2* qcur = phh;   // nominal vin for first pass (also used as hh source)
    __half2* qout = pq0;
    __half2* qalt = pq1;
    for (int j = KORD - 1; j >= 1; j--) {
        spmv_h_k<<<warp_blocks, 256>>>(qcur, qout, phh, ph, j);
        qcur = qout;
        __half2* t = qout == pq0 ? pq1 : pq0;
        qout = t;
        (void)qalt;
    }
    spmv_lsm_k<<<warp_blocks, 256>>>(qcur, out, ph);
}

// round 16
// speedup vs baseline: 4.0765x; 1.2404x over previous
#include <cuda_runtime.h>
#include <cuda_fp16.h>
#include <math.h>
#include <stdint.h>

#define N_NODES 100000
#define N_EDGES 3200000
#define D_IN    512
#define D_HID   256
#define D_OUT   64
#define KORD    10

#define SCAN_CHUNK   1024
#define NSCAN_BLOCKS 98          // ceil(100000/1024)

// ---------------- device scratch (no allocations allowed) ----------------
__device__ int     g_cnt[N_NODES];
__device__ int     g_pos[N_NODES];
__device__ int     g_start[N_NODES + 1];
__device__ float   g_dinv[N_NODES];
__device__ int     g_bsum[NSCAN_BLOCKS];
__device__ int     g_bflag[NSCAN_BLOCKS];
__device__ int2    g_edge[N_EDGES];                        // (col, w bits) CSR by row
__device__ __half  g_w1h[(size_t)D_HID * D_IN];            // W1^T fp16 [256][512]
__device__ __half  g_w2h[(size_t)D_OUT * D_HID];           // W2^T fp16 [64][256]
__device__ __half  g_h1h[(size_t)N_NODES * D_HID];         // MLP hidden fp16
__device__ float   g_h [(size_t)N_NODES * D_OUT];          // MLP output fp32
__device__ __half2 g_hh[(size_t)N_NODES * (D_OUT / 2)];    // MLP output fp16
__device__ __half2 g_q0[(size_t)N_NODES * (D_OUT / 2)];    // Horner intermediates (fp16)
__device__ __half2 g_q1[(size_t)N_NODES * (D_OUT / 2)];
__device__ float   g_coef[KORD + 1];                       // monomial coeffs of poly in A
__device__ int     g_deg;                                  // true polynomial degree

// binomial coefficients C(n,k), n<=10 (exact integers)
__constant__ int c_comb[11][11] = {
    {1,0,0,0,0,0,0,0,0,0,0},
    {1,1,0,0,0,0,0,0,0,0,0},
    {1,2,1,0,0,0,0,0,0,0,0},
    {1,3,3,1,0,0,0,0,0,0,0},
    {1,4,6,4,1,0,0,0,0,0,0},
    {1,5,10,10,5,1,0,0,0,0,0},
    {1,6,15,20,15,6,1,0,0,0,0},
    {1,7,21,35,35,21,7,1,0,0,0},
    {1,8,28,56,70,56,28,8,1,0,0},
    {1,9,36,84,126,126,84,36,9,1,0},
    {1,10,45,120,210,252,210,120,45,10,1}
};

// ---------------- fused prep: convW1 + convW2 + zero cnt + flags + coef/degree ----------------
// grid = 512 (convW1) + 64 (convW2) + 391 (zero cnt) + 1 (flags + coef) = 968 blocks x 256
__global__ void prep_k(const float* __restrict__ W1, const float* __restrict__ W2,
                       const float* __restrict__ temp) {
    int b = blockIdx.x, tid = threadIdx.x;
    if (b < 512) {                               // W1 [512][256] -> W1^T fp16
        int i = b * 256 + tid;
        int k = i >> 8, n = i & 255;
        g_w1h[(size_t)n * D_IN + k] = __float2half_rn(W1[i]);
    } else if (b < 576) {                        // W2 [256][64] -> W2^T fp16
        int i = (b - 512) * 256 + tid;
        int k = i >> 6, n = i & 63;
        g_w2h[(size_t)n * D_HID + k] = __float2half_rn(W2[i]);
    } else if (b < 967) {                        // zero degree counts
        int i = (b - 576) * 256 + tid;
        if (i < N_NODES) g_cnt[i] = 0;
    } else {                                     // scan flags + Bernstein->monomial coeffs
        if (tid < NSCAN_BLOCKS) g_bflag[tid] = 0;
        __shared__ double sa[121];
        __shared__ int sdeg;
        if (tid == 0) sdeg = 0;
        if (tid < 121) {
            int k = tid / 11, j = tid % 11;
            double th = (double)temp[k];
            if (th < 0.0) th = 0.0;              // relu
            double ck = th * (double)c_comb[10][k] / 1024.0;
            double s = 0.0;
            for (int i2 = 0; i2 <= k; i2++) {
                int l = j - i2;
                if (l >= 0 && l <= 10 - k) {
                    double t = (double)c_comb[k][i2] * (double)c_comb[10 - k][l];
                    s += (i2 & 1) ? -t : t;
                }
            }
            sa[tid] = ck * s;
        }
        __syncthreads();
        if (tid < 11) {
            double a = 0.0;
            for (int k = 0; k < 11; k++) a += sa[k * 11 + tid];
            g_coef[tid] = (float)a;
            if (a != 0.0) atomicMax(&sdeg, tid);  // exact-zero test (integer convs + /2^10)
        }
        __syncthreads();
        if (tid == 0) g_deg = sdeg;
    }
}

// ---------------- CSR build (skipped entirely when degree == 0) ----------------
// 2 edges per thread
__global__ void hist_k(const int* __restrict__ row) {
    if (g_deg == 0) return;
    int t = blockIdx.x * blockDim.x + threadIdx.x;
    int e0 = t * 2;
    if (e0 >= N_EDGES) return;
    int2 r2 = *reinterpret_cast<const int2*>(&row[e0]);
    atomicAdd(&g_cnt[r2.x], 1);
    atomicAdd(&g_cnt[r2.y], 1);
}

// single-kernel exclusive scan via decoupled lookback (98 blocks, all co-resident)
__global__ void scanL_k() {
    if (g_deg == 0) return;
    __shared__ int ws[8];
    __shared__ int s_goff;
    int b = blockIdx.x, tid = threadIdx.x;
    int lane = tid & 31, warp = tid >> 5;
    if (tid == 0) s_goff = 0;
    int base = b * SCAN_CHUNK + tid * 4;
    int v[4];
    int ts = 0;
#pragma unroll
    for (int q = 0; q < 4; q++) {
        int i = base + q;
        v[q] = (i < N_NODES) ? g_cnt[i] : 0;
        ts += v[q];
    }
    int incl = ts;
#pragma unroll
    for (int o = 1; o < 32; o <<= 1) {
        int t = __shfl_up_sync(0xFFFFFFFFu, incl, o);
        if (lane >= o) incl += t;
    }
    if (lane == 31) ws[warp] = incl;
    __syncthreads();
    if (warp == 0 && lane < 8) {
        int w = ws[lane];
#pragma unroll
        for (int o = 1; o < 8; o <<= 1) {
            int t = __shfl_up_sync(0xFFu, w, o);
            if (lane >= o) w += t;
        }
        ws[lane] = w;
    }
    __syncthreads();
    // publish this block's aggregate
    if (tid == 0) {
        g_bsum[b] = ws[7];
        __threadfence();
        atomicExch(&g_bflag[b], 1);
    }
    // lookback: thread t waits for block t (t < b), sums aggregates
    if (tid < b) {
        while (atomicAdd(&g_bflag[tid], 0) == 0) {}
        atomicAdd(&s_goff, atomicAdd(&g_bsum[tid], 0));
    }
    __syncthreads();
    int off = s_goff + ((warp > 0) ? ws[warp - 1] : 0) + (incl - ts);
#pragma unroll
    for (int q = 0; q < 4; q++) {
        int i = base + q;
        if (i < N_NODES) {
            g_start[i] = off;
            g_pos[i]   = off;
            g_dinv[i]  = (v[q] > 0) ? rsqrtf((float)v[q]) : 0.0f;
        }
        off += v[q];
    }
    if (b == 0 && tid == 0) g_start[N_NODES] = N_EDGES;
}

// 2 edges per thread
__global__ void scatter_k(const int* __restrict__ row, const int* __restrict__ col) {
    if (g_deg == 0) return;
    int t = blockIdx.x * blockDim.x + threadIdx.x;
    int e0 = t * 2;
    if (e0 >= N_EDGES) return;
    int2 r2 = *reinterpret_cast<const int2*>(&row[e0]);
    int2 c2 = *reinterpret_cast<const int2*>(&col[e0]);
    int p0 = atomicAdd(&g_pos[r2.x], 1);
    g_edge[p0] = make_int2(c2.x, __float_as_int(g_dinv[r2.x] * g_dinv[c2.x]));
    int p1 = atomicAdd(&g_pos[r2.y], 1);
    g_edge[p1] = make_int2(c2.y, __float_as_int(g_dinv[r2.y] * g_dinv[c2.y]));
}

// ---------------- fp16 tensor-core GEMM (mma.sync m16n8k16 + ldmatrix) ----------------
__device__ __forceinline__ void mma_f16(float* d, const uint32_t* a, const uint32_t* b) {
    asm volatile(
        "mma.sync.aligned.m16n8k16.row.col.f32.f16.f16.f32 "
        "{%0,%1,%2,%3}, {%4,%5,%6,%7}, {%8,%9}, {%0,%1,%2,%3};"
        : "+f"(d[0]), "+f"(d[1]), "+f"(d[2]), "+f"(d[3])
        : "r"(a[0]), "r"(a[1]), "r"(a[2]), "r"(a[3]), "r"(b[0]), "r"(b[1]));
}

__device__ __forceinline__ void ldsm_x4(uint32_t* r, uint32_t addr) {
    asm volatile("ldmatrix.sync.aligned.m8n8.x4.shared.b16 {%0,%1,%2,%3}, [%4];"
                 : "=r"(r[0]), "=r"(r[1]), "=r"(r[2]), "=r"(r[3]) : "r"(addr));
}

// A: [M,Kd] row-major (fp32 if AF32, converted inline; else fp16).
// Bt: [Nd,Kd] fp16 (pre-transposed). C = relu?(A@B + bias).
// WF: write fp32 C ; WH: write fp16 copy to Ch.
template <int BM, int BN, int WM, int WN, bool AF32, bool RELU, bool WF, bool WH>
__launch_bounds__(256)
__global__ void gemm_h_k(const void* __restrict__ Ain, const __half* __restrict__ Bt,
                         const float* __restrict__ bias, float* __restrict__ C,
                         __half2* __restrict__ Ch, int M, int Kd, int Nd) {
    constexpr int BK = 32;
    constexpr int APITCH = BK + 8;                 // 40 halves = 80 bytes (16B-aligned rows)
    constexpr int BPITCH = BK + 8;
    constexpr int WTM = BM / WM;
    constexpr int WTN = BN / WN;
    constexpr int MT = WTM / 16;
    constexpr int NT = WTN / 8;                    // must be even (paired ldmatrix.x4)
    static_assert(NT % 2 == 0, "NT even");
    constexpr int AV4 = (BM * BK) / (256 * 4);
    constexpr int AVH = (BM * BK) / (256 * 8);
    constexpr int BV  = (BN * BK) / (256 * 8);

    __shared__ __align__(16) __half As[BM * APITCH];
    __shared__ __align__(16) __half Bs[BN * BPITCH];

    const float*  Af = (const float*)Ain;
    const __half* Ah = (const __half*)Ain;

    const int tid  = threadIdx.x;
    const int lane = tid & 31;
    const int w    = tid >> 5;
    const int wm   = w % WM;
    const int wn   = w / WM;
    const int m0   = blockIdx.y * BM;
    const int n0   = blockIdx.x * BN;

    float acc[MT][NT][4];
#pragma unroll
    for (int i = 0; i < MT; i++)
#pragma unroll
        for (int j = 0; j < NT; j++)
#pragma unroll
            for (int q = 0; q < 4; q++) acc[i][j][q] = 0.0f;

    // ldmatrix per-thread base addresses (bytes, shared space)
    const uint32_t asB = (uint32_t)__cvta_generic_to_shared(As);
    const uint32_t bsB = (uint32_t)__cvta_generic_to_shared(Bs);
    const uint32_t aBase = asB + (uint32_t)(((wm * WTM + (lane & 15)) * APITCH + (lane >> 4) * 8) * 2);
    const uint32_t bBase = bsB + (uint32_t)(((wn * WTN + (lane & 7) + ((lane & 16) ? 8 : 0)) * BPITCH
                                             + ((lane >> 3) & 1) * 8) * 2);

    float4 aSf[AF32 ? AV4 : 1];
    uint4  aSh[AF32 ? 1 : AVH];
    uint4  bS[BV];

    // prefetch tile 0
    if (AF32) {
#pragma unroll
        for (int i = 0; i < AV4; i++) {
            int idx = tid + i * 256;
            int r = idx >> 3, c = (idx & 7) * 4;
            int gm = min(m0 + r, M - 1);
            aSf[i] = *reinterpret_cast<const float4*>(&Af[(size_t)gm * Kd + c]);
        }
    } else {
#pragma unroll
        for (int i = 0; i < AVH; i++) {
            int idx = tid + i * 256;
            int r = idx >> 2, c = (idx & 3) * 8;
            int gm = min(m0 + r, M - 1);
            aSh[i] = *reinterpret_cast<const uint4*>(&Ah[(size_t)gm * Kd + c]);
        }
    }
#pragma unroll
    for (int i = 0; i < BV; i++) {
        int idx = tid + i * 256;
        int n = idx >> 2, kg = (idx & 3) * 8;
        bS[i] = *reinterpret_cast<const uint4*>(&Bt[(size_t)(n0 + n) * Kd + kg]);
    }

    for (int kt = 0; kt < Kd; kt += BK) {
        // stage regs -> smem
        if (AF32) {
#pragma unroll
            for (int i = 0; i < AV4; i++) {
                int idx = tid + i * 256;
                int r = idx >> 3, c = (idx & 7) * 4;
                __half2 lo = __floats2half2_rn(aSf[i].x, aSf[i].y);
                __half2 hi = __floats2half2_rn(aSf[i].z, aSf[i].w);
                *reinterpret_cast<uint2*>(&As[r * APITCH + c]) =
                    make_uint2(*(uint32_t*)&lo, *(uint32_t*)&hi);
            }
        } else {
#pragma unroll
            for (int i = 0; i < AVH; i++) {
                int idx = tid + i * 256;
                int r = idx >> 2, c = (idx & 3) * 8;
                *reinterpret_cast<uint4*>(&As[r * APITCH + c]) = aSh[i];
            }
        }
#pragma unroll
        for (int i = 0; i < BV; i++) {
            int idx = tid + i * 256;
            int n = idx >> 2, kg = (idx & 3) * 8;
            *reinterpret_cast<uint4*>(&Bs[n * BPITCH + kg]) = bS[i];
        }
        __syncthreads();

        // prefetch next tile
        if (kt + BK < Kd) {
            if (AF32) {
#pragma unroll
                for (int i = 0; i < AV4; i++) {
                    int idx = tid + i * 256;
                    int r = idx >> 3, c = (idx & 7) * 4;
                    int gm = min(m0 + r, M - 1);
                    aSf[i] = *reinterpret_cast<const float4*>(&Af[(size_t)gm * Kd + kt + BK + c]);
                }
            } else {
#pragma unroll
                for (int i = 0; i < AVH; i++) {
                    int idx = tid + i * 256;
                    int r = idx >> 2, c = (idx & 3) * 8;
                    int gm = min(m0 + r, M - 1);
                    aSh[i] = *reinterpret_cast<const uint4*>(&Ah[(size_t)gm * Kd + kt + BK + c]);
                }
            }
#pragma unroll
            for (int i = 0; i < BV; i++) {
                int idx = tid + i * 256;
                int n = idx >> 2, kg = (idx & 3) * 8;
                bS[i] = *reinterpret_cast<const uint4*>(&Bt[(size_t)(n0 + n) * Kd + kt + BK + kg]);
            }
        }

        // compute: 2 chunks of k16, fragments via ldmatrix
#pragma unroll
        for (int ch = 0; ch < 2; ch++) {
            uint32_t afr[MT][4], bfr[NT][2];
#pragma unroll
            for (int mt = 0; mt < MT; mt++)
                ldsm_x4(afr[mt], aBase + mt * 16 * APITCH * 2 + ch * 32);
#pragma unroll
            for (int np = 0; np < NT / 2; np++) {
                uint32_t t4[4];
                ldsm_x4(t4, bBase + np * 16 * BPITCH * 2 + ch * 32);
                bfr[2 * np][0] = t4[0];
                bfr[2 * np][1] = t4[1];
                bfr[2 * np + 1][0] = t4[2];
                bfr[2 * np + 1][1] = t4[3];
            }
#pragma unroll
            for (int mt = 0; mt < MT; mt++)
#pragma unroll
                for (int nt = 0; nt < NT; nt++)
                    mma_f16(acc[mt][nt], afr[mt], bfr[nt]);
        }
        __syncthreads();
    }

    // epilogue: bias (+relu)
#pragma unroll
    for (int mt = 0; mt < MT; mt++) {
#pragma unroll
        for (int nt = 0; nt < NT; nt++) {
            int col = n0 + wn * WTN + nt * 8 + (lane & 3) * 2;
            float bx = bias[col], by = bias[col + 1];
            int r0 = m0 + wm * WTM + mt * 16 + (lane >> 2);
            float vx = acc[mt][nt][0] + bx;
            float vy = acc[mt][nt][1] + by;
            if (RELU) { vx = fmaxf(vx, 0.0f); vy = fmaxf(vy, 0.0f); }
            if (r0 < M) {
                if (WF) *reinterpret_cast<float2*>(&C[(size_t)r0 * Nd + col]) = make_float2(vx, vy);
                if (WH) Ch[((size_t)r0 * Nd + col) >> 1] = __floats2half2_rn(vx, vy);
            }
            int r1 = r0 + 8;
            vx = acc[mt][nt][2] + bx;
            vy = acc[mt][nt][3] + by;
            if (RELU) { vx = fmaxf(vx, 0.0f); vy = fmaxf(vy, 0.0f); }
            if (r1 < M) {
                if (WF) *reinterpret_cast<float2*>(&C[(size_t)r1 * Nd + col]) = make_float2(vx, vy);
                if (WH) Ch[((size_t)r1 * Nd + col) >> 1] = __floats2half2_rn(vx, vy);
            }
        }
    }
}

// ---------------- Horner SpMV (fp16 gather, fp32 accumulate) ----------------
__device__ __forceinline__ void spmv_body(const __half2* __restrict__ vin,
                                          const float* __restrict__ h,
                                          int jadd, float gm, int wid, int lane,
                                          float& accx, float& accy) {
    float aj = g_coef[jadd];
    float2 hv = reinterpret_cast<const float2*>(h)[(size_t)wid * 32 + lane];
    accx = aj * hv.x;
    accy = aj * hv.y;
    int idx = g_start[wid];
    int e   = g_start[wid + 1];
    for (; idx + 16 <= e; idx += 16) {
        int2 ed[16];
        __half2 gv[16];
#pragma unroll
        for (int q = 0; q < 16; q++) ed[q] = g_edge[idx + q];
#pragma unroll
        for (int q = 0; q < 16; q++) gv[q] = vin[(size_t)ed[q].x * 32 + lane];
#pragma unroll
        for (int q = 0; q < 16; q++) {
            float w = gm * __int_as_float(ed[q].y);
            float2 f = __half22float2(gv[q]);
            accx = fmaf(w, f.x, accx);
            accy = fmaf(w, f.y, accy);
        }
    }
    for (; idx + 4 <= e; idx += 4) {
        int2 ed[4];
        __half2 gv[4];
#pragma unroll
        for (int q = 0; q < 4; q++) ed[q] = g_edge[idx + q];
#pragma unroll
        for (int q = 0; q < 4; q++) gv[q] = vin[(size_t)ed[q].x * 32 + lane];
#pragma unroll
        for (int q = 0; q < 4; q++) {
            float w = gm * __int_as_float(ed[q].y);
            float2 f = __half22float2(gv[q]);
            accx = fmaf(w, f.x, accx);
            accy = fmaf(w, f.y, accy);
        }
    }
    for (; idx < e; ++idx) {
        int2 ed = g_edge[idx];
        float w = gm * __int_as_float(ed.y);
        float2 f = __half22float2(vin[(size_t)ed.x * 32 + lane]);
        accx = fmaf(w, f.x, accx);
        accy = fmaf(w, f.y, accy);
    }
}

// Adaptive-degree Horner pass for coefficient index jpass (K-1 .. 1):
//   jpass > d : no-op ; jpass == d : vout = a_d * h (flat copy) ; jpass < d : gather pass
__launch_bounds__(512)
__global__ void spmv_h_k(const __half2* __restrict__ vin, __half2* __restrict__ vout,
                         const __half2* __restrict__ hh, const float* __restrict__ h,
                         int jpass) {
    int d = g_deg;
    if (jpass > d) return;
    int gidx = blockIdx.x * blockDim.x + threadIdx.x;
    if (jpass == d) {
        if (gidx < N_NODES * 32) {
            float a = g_coef[d];
            float2 f = __half22float2(hh[gidx]);
            vout[gidx] = __floats2half2_rn(a * f.x, a * f.y);
        }
        return;
    }
    int wid  = gidx >> 5;
    int lane = threadIdx.x & 31;
    if (wid >= N_NODES) return;
    bool first = (jpass == KORD - 1);          // only reachable when d == KORD
    const __half2* vsrc = first ? hh : vin;
    float gm = first ? g_coef[KORD] : 1.0f;
    float accx, accy;
    spmv_body(vsrc, h, jpass, gm, wid, lane, accx, accy);
    vout[(size_t)wid * 32 + lane] = __floats2half2_rn(accx, accy);
}

// final pass (j = 0) fused with log_softmax; skips gather entirely when d == 0
__launch_bounds__(512)
__global__ void spmv_lsm_k(const __half2* __restrict__ vin, float* __restrict__ out,
                           const float* __restrict__ h) {
    int wid  = (blockIdx.x * blockDim.x + threadIdx.x) >> 5;
    int lane = threadIdx.x & 31;
    if (wid >= N_NODES) return;
    float vx, vy;
    if (g_deg == 0) {
        float a0 = g_coef[0];
        float2 hv = reinterpret_cast<const float2*>(h)[(size_t)wid * 32 + lane];
        vx = a0 * hv.x;
        vy = a0 * hv.y;
    } else {
        spmv_body(vin, h, 0, 1.0f, wid, lane, vx, vy);
    }
    float m = fmaxf(vx, vy);
#pragma unroll
    for (int o = 16; o; o >>= 1) m = fmaxf(m, __shfl_xor_sync(0xFFFFFFFFu, m, o));
    float s = expf(vx - m) + expf(vy - m);
#pragma unroll
    for (int o = 16; o; o >>= 1) s += __shfl_xor_sync(0xFFFFFFFFu, s, o);
    float l = m + logf(s);
    reinterpret_cast<float2*>(out)[(size_t)wid * 32 + lane] = make_float2(vx - l, vy - l);
}

// ---------------- launcher ----------------
extern "C" void kernel_launch(void* const* d_in, const int* in_sizes, int n_in,
                              void* d_out, int out_size) {
    const float* x    = (const float*)d_in[0];
    const int*   ei   = (const int*)  d_in[1];
    const float* W1   = (const float*)d_in[2];
    const float* b1   = (const float*)d_in[3];
    const float* W2   = (const float*)d_in[4];
    const float* b2   = (const float*)d_in[5];
    const float* temp = (const float*)d_in[6];
    float*       out  = (float*)d_out;
    const int* row = ei;
    const int* col = ei + N_EDGES;

    float *ph;
    __half *pw1h, *pw2h, *ph1h;
    __half2 *phh, *pq0, *pq1;
    cudaGetSymbolAddress((void**)&pw1h, g_w1h);
    cudaGetSymbolAddress((void**)&pw2h, g_w2h);
    cudaGetSymbolAddress((void**)&ph1h, g_h1h);
    cudaGetSymbolAddress((void**)&ph,   g_h);
    cudaGetSymbolAddress((void**)&phh,  g_hh);
    cudaGetSymbolAddress((void**)&pq0,  g_q0);
    cudaGetSymbolAddress((void**)&pq1,  g_q1);

    // 1: fused prep (weights fp16^T, coeffs + degree, cnt zero, scan flags)
    prep_k<<<968, 256>>>(W1, W2, temp);
    // 2-3: CSR histogram + single-kernel lookback scan (early-exit when deg==0)
    hist_k<<<(N_EDGES / 2 + 255) / 256, 256>>>(row);
    scanL_k<<<NSCAN_BLOCKS, 256>>>();
    // 4: GEMM1 (ncu target slot)
    {
        dim3 g1(D_HID / 128, (N_NODES + 127) / 128);
        gemm_h_k<128, 128, 2, 4, true, true, false, true>
            <<<g1, 256>>>(x, pw1h, b1, nullptr, (__half2*)ph1h, N_NODES, D_IN, D_HID);
    }
    // 5: CSR scatter
    scatter_k<<<(N_EDGES / 2 + 255) / 256, 256>>>(row, col);
    // 6: GEMM2 (fp16 in, fp32 + fp16 out)
    {
        dim3 g2(D_OUT / 64, (N_NODES + 127) / 128);
        gemm_h_k<128, 64, 4, 2, false, false, true, true>
            <<<g2, 256>>>(ph1h, pw2h, b2, ph, phh, N_NODES, D_HID, D_OUT);
    }

    // Adaptive-degree Horner: passes j = K-1 .. 1, then fused lsm pass (j = 0)
    const int blocks512 = (N_NODES * 32 + 511) / 512;   // 6250
    __half2* qcur = phh;
    __half2* qout = pq0;
    for (int j = KORD - 1; j >= 1; j--) {
        spmv_h_k<<<blocks512, 512>>>(qcur, qout, phh, ph, j);
        qcur = qout;
        qout = (qout == pq0) ? pq1 : pq0;
    }
    spmv_lsm_k<<<blocks512, 512>>>(qcur, out, ph);
}